// round 8
// baseline (speedup 1.0000x reference)
#include <cuda_runtime.h>
#include <cstdint>
#include <cstddef>

#define S_LEN 4096
#define D_DIM 2048
#define V_DIM 64000
#define NBINS 32768
#define BIN_SMEM 2048

// ---------------- static scratch (no allocations allowed) ----------------
__device__ float  g_s[S_LEN];
__device__ float  g_scores[S_LEN];
__device__ double g_pool_part[64][D_DIM];
__device__ float  g_pooled[D_DIM];
__device__ double g_logit_part[4][V_DIM];
__device__ float  g_logits[V_DIM];
__device__ float  g_maxl;
__device__ float  g_e[V_DIM];
__device__ double g_zpart[256];
__device__ float  g_Z;
__device__ unsigned g_key[V_DIM];
__device__ unsigned g_hist[NBINS];
__device__ unsigned g_base[NBINS];
__device__ unsigned g_fill[NBINS];
__device__ int      g_nbins;
__device__ int      g_binlist[NBINS];
__device__ unsigned g_slotkey[V_DIM];
__device__ int      g_slotidx[V_DIM];
__device__ float    g_sortp[V_DIM];
__device__ int      g_order[V_DIM];
__device__ unsigned char g_mask[V_DIM];
__device__ unsigned long long g_best;

// ---------------- threefry2x32 (bit-exact JAX PRNG) ----------------
__device__ __forceinline__ uint32_t rotl32(uint32_t v, int n) {
    return (v << n) | (v >> (32 - n));
}

__device__ __forceinline__ void threefry2x32(uint32_t k0, uint32_t k1,
                                             uint32_t& x0, uint32_t& x1) {
    uint32_t ks[3] = {k0, k1, k0 ^ k1 ^ 0x1BD11BDAu};
    const int rotA[4] = {13, 15, 26, 6};
    const int rotB[4] = {17, 29, 16, 24};
    x0 += ks[0]; x1 += ks[1];
#pragma unroll
    for (int i = 0; i < 5; i++) {
        const int* r = (i & 1) ? rotB : rotA;
#pragma unroll
        for (int k = 0; k < 4; k++) {
            x0 += x1;
            x1 = rotl32(x1, r[k]);
            x1 ^= x0;
        }
        x0 += ks[(i + 1) % 3];
        x1 += ks[(i + 2) % 3] + (uint32_t)(i + 1);
    }
}

// ---------------- kernels ----------------
__global__ void k_init() {
    int i = blockIdx.x * blockDim.x + threadIdx.x;
    if (i < NBINS) { g_hist[i] = 0u; g_fill[i] = 0u; }
    if (i == 0) { g_best = 0ull; g_nbins = 0; }
}

// s[j] = batch[j,:] . pool_w  (exact fp32 products, order-free fp64 accumulate)
__global__ void k_scoredot(const float* __restrict__ batch,
                           const float* __restrict__ pw) {
    int j = blockIdx.x;
    const float* row = batch + (size_t)j * D_DIM;
    int t = threadIdx.x;  // 256
    double acc = 0.0;
#pragma unroll
    for (int k = 0; k < 8; k++) {
        int d = t + k * 256;
        acc += (double)(row[d] * pw[d]);
    }
    __shared__ double sm[256];
    sm[t] = acc;
    __syncthreads();
    for (int o = 128; o > 0; o >>= 1) {
        if (t < o) sm[t] += sm[t + o];
        __syncthreads();
    }
    if (t == 0) g_s[j] = (float)sm[0];
}

// softmax over S (single block); expf matches libdevice exp
__global__ void k_softmax_scores() {
    __shared__ float smx[1024];
    __shared__ double smd[1024];
    int t = threadIdx.x;
    float m = -3.4e38f;
    for (int i = t; i < S_LEN; i += 1024) m = fmaxf(m, g_s[i]);
    smx[t] = m;
    __syncthreads();
    for (int o = 512; o > 0; o >>= 1) {
        if (t < o) smx[t] = fmaxf(smx[t], smx[t + o]);
        __syncthreads();
    }
    float gm = smx[0];
    __syncthreads();
    double sum = 0.0;
    for (int i = t; i < S_LEN; i += 1024) {
        float e = expf(g_s[i] - gm);
        g_scores[i] = e;
        sum += (double)e;
    }
    smd[t] = sum;
    __syncthreads();
    for (int o = 512; o > 0; o >>= 1) {
        if (t < o) smd[t] += smd[t + o];
        __syncthreads();
    }
    float Z = (float)smd[0];
    __syncthreads();
    for (int i = t; i < S_LEN; i += 1024) g_scores[i] = g_scores[i] / Z;
}

// pooled partials (exact einsum "bs,bsd->bd"): fp32 products, fp64 accumulate
__global__ void k_pool_part(const float* __restrict__ batch) {
    int d = blockIdx.x * 128 + threadIdx.x;  // grid.x = 16
    int c = blockIdx.y;                       // 0..63
    int j0 = c * 64;
    double acc = 0.0;
#pragma unroll 4
    for (int jj = 0; jj < 64; jj++) {
        int j = j0 + jj;
        acc += (double)(g_scores[j] * batch[(size_t)j * D_DIM + d]);
    }
    g_pool_part[c][d] = acc;
}

__global__ void k_pool_reduce() {
    int d = blockIdx.x * 256 + threadIdx.x;  // grid 8
    double s = 0.0;
    for (int c = 0; c < 64; c++) s += g_pool_part[c][d];
    g_pooled[d] = (float)s;  // correctly-rounded fp32 pooled
}

// big GEMV (exact projection pooled @ W): fp32 products via fp64 accumulation
// using 8 interleaved fp32 accumulators + fp64 combine (noise ~e-9 << gaps)
__global__ void k_logits_part(const float* __restrict__ W) {
    int v = blockIdx.x * 256 + threadIdx.x;  // grid.x = 250
    int seg = blockIdx.y;                     // 0..3
    int d0 = seg * 512;
    __shared__ float sp[512];
    for (int i = threadIdx.x; i < 512; i += 256) sp[i] = g_pooled[d0 + i];
    __syncthreads();
    const float* wp = W + (size_t)d0 * V_DIM + v;
    double a0 = 0.0, a1 = 0.0, a2 = 0.0, a3 = 0.0;
#pragma unroll 4
    for (int d = 0; d < 512; d += 4) {
        size_t base = (size_t)d * V_DIM;
        float w0 = wp[base + 0 * (size_t)V_DIM];
        float w1 = wp[base + 1 * (size_t)V_DIM];
        float w2 = wp[base + 2 * (size_t)V_DIM];
        float w3 = wp[base + 3 * (size_t)V_DIM];
        a0 += (double)(sp[d + 0] * w0);
        a1 += (double)(sp[d + 1] * w1);
        a2 += (double)(sp[d + 2] * w2);
        a3 += (double)(sp[d + 3] * w3);
    }
    g_logit_part[seg][v] = (a0 + a1) + (a2 + a3);
}

__global__ void k_logits_final(const float* __restrict__ b) {
    int v = blockIdx.x * 256 + threadIdx.x;  // grid 250
    double s = g_logit_part[0][v] + g_logit_part[1][v] +
               g_logit_part[2][v] + g_logit_part[3][v];
    float m = (float)s;
    m = m + b[v];            // reference adds bias in fp32
    g_logits[v] = 0.7f * m;  // TEMPERATURE
}

__global__ void k_maxl() {
    __shared__ float sm[1024];
    int t = threadIdx.x;
    float m = -3.4e38f;
    for (int i = t; i < V_DIM; i += 1024) m = fmaxf(m, g_logits[i]);
    sm[t] = m;
    __syncthreads();
    for (int o = 512; o > 0; o >>= 1) {
        if (t < o) sm[t] = fmaxf(sm[t], sm[t + o]);
        __syncthreads();
    }
    if (t == 0) g_maxl = sm[0];
}

__global__ void k_exp() {
    int v = blockIdx.x * 256 + threadIdx.x;
    float e = expf(g_logits[v] - g_maxl);
    g_e[v] = e;
    __shared__ double sd[256];
    sd[threadIdx.x] = (double)e;
    __syncthreads();
    for (int o = 128; o > 0; o >>= 1) {
        if (threadIdx.x < o) sd[threadIdx.x] += sd[threadIdx.x + o];
        __syncthreads();
    }
    if (threadIdx.x == 0) g_zpart[blockIdx.x] = sd[0];
}

__global__ void k_zred() {
    __shared__ double sd[256];
    int t = threadIdx.x;
    sd[t] = (t < 250) ? g_zpart[t] : 0.0;
    __syncthreads();
    for (int o = 128; o > 0; o >>= 1) {
        if (t < o) sd[t] += sd[t + o];
        __syncthreads();
    }
    if (t == 0) g_Z = (float)sd[0];
}

__global__ void k_phist() {
    int v = blockIdx.x * 256 + threadIdx.x;
    float p = g_e[v] / g_Z;             // IEEE fp32 division
    unsigned key = __float_as_uint(p);  // p > 0 -> bits monotone in value
    g_key[v] = key;
    atomicAdd(&g_hist[key >> 17], 1u);
}

// suffix-exclusive scan over 32768 bins + occupied-bin list
__global__ void k_scan() {
    __shared__ unsigned ssum[1024];
    int t = threadIdx.x;
    unsigned local = 0;
    for (int k = 0; k < 32; k++) local += g_hist[t * 32 + k];
    ssum[t] = local;
    __syncthreads();
    for (int off = 1; off < 1024; off <<= 1) {
        unsigned add = (t >= off) ? ssum[t - off] : 0u;
        __syncthreads();
        ssum[t] += add;
        __syncthreads();
    }
    unsigned total = ssum[1023];
    unsigned suffix = total - ssum[t];
    unsigned running = suffix;
    for (int k = 31; k >= 0; k--) {
        int b = t * 32 + k;
        g_base[b] = running;
        unsigned h = g_hist[b];
        running += h;
        if (h > 0) {
            int p = atomicAdd(&g_nbins, 1);
            g_binlist[p] = b;
        }
    }
}

__global__ void k_scatter() {
    int v = blockIdx.x * 256 + threadIdx.x;
    unsigned key = g_key[v];
    unsigned b = key >> 17;
    unsigned pos = g_base[b] + atomicAdd(&g_fill[b], 1u);
    g_slotkey[pos] = key;
    g_slotidx[pos] = v;
}

// exact rank within bin: descending key, ties by ascending original index
__global__ void k_rank() {
    __shared__ unsigned sk[BIN_SMEM];
    __shared__ int si[BIN_SMEM];
    int nb = g_nbins;
    for (int bi = blockIdx.x; bi < nb; bi += gridDim.x) {
        int b = g_binlist[bi];
        unsigned c = g_hist[b];
        unsigned base = g_base[b];
        if (c <= BIN_SMEM) {
            for (unsigned e = threadIdx.x; e < c; e += blockDim.x) {
                sk[e] = g_slotkey[base + e];
                si[e] = g_slotidx[base + e];
            }
            __syncthreads();
            for (unsigned e = threadIdx.x; e < c; e += blockDim.x) {
                unsigned ke = sk[e];
                int ide = si[e];
                unsigned r = 0;
                for (unsigned u = 0; u < c; u++) {
                    unsigned ku = sk[u];
                    r += (ku > ke) || (ku == ke && si[u] < ide);
                }
                g_sortp[base + r] = __uint_as_float(ke);
                g_order[base + r] = ide;
            }
            __syncthreads();
        } else {
            for (unsigned e = threadIdx.x; e < c; e += blockDim.x) {
                unsigned ke = g_slotkey[base + e];
                int ide = g_slotidx[base + e];
                unsigned r = 0;
                for (unsigned u = 0; u < c; u++) {
                    unsigned ku = g_slotkey[base + u];
                    r += (ku > ke) || (ku == ke && g_slotidx[base + u] < ide);
                }
                g_sortp[base + r] = __uint_as_float(ke);
                g_order[base + r] = ide;
            }
            __syncthreads();
        }
    }
}

// inclusive cumsum (fp64) + top-p mask
__global__ void k_cummask() {
    __shared__ double sd[1024];
    int t = threadIdx.x;
    int i0 = t * 64;
    double s = 0.0;
    for (int k = 0; k < 64; k++) {
        int i = i0 + k;
        if (i < V_DIM) s += (double)g_sortp[i];
    }
    sd[t] = s;
    __syncthreads();
    for (int off = 1; off < 1024; off <<= 1) {
        double add = (t >= off) ? sd[t - off] : 0.0;
        __syncthreads();
        sd[t] += add;
        __syncthreads();
    }
    double run = (t > 0) ? sd[t - 1] : 0.0;
    for (int k = 0; k < 64; k++) {
        int i = i0 + k;
        if (i < V_DIM) {
            run += (double)g_sortp[i];
            g_mask[i] = (run <= 0.5) ? 1 : 0;
        }
    }
}

// gumbel-argmax over masked positions.
// JAX partitionable threefry (default since 0.4.36), 32-bit path:
//   counts = iota(uint64); (y0,y1) = threefry2x32(key, (hi32(i), lo32(i)))
//   bit_width in [8,16,32]: draw = convert_element_type(y0 ^ y1, uint32)
__global__ void k_argmax() {
    int i = blockIdx.x * 256 + threadIdx.x;
    if (i >= V_DIM) return;
    if (!g_mask[i]) return;
    uint32_t x0 = 0u, x1 = (uint32_t)i;
    threefry2x32(0u, 42u, x0, x1);
    uint32_t bits = x0 ^ x1;  // XOR fold of both output lanes
    float f = __uint_as_float((bits >> 9) | 0x3f800000u) - 1.0f;  // [0,1)
    float u = (f > 0.0f) ? f : 1.17549435e-38f;                    // jax minval=tiny
    float g = -logf(-logf(u));
    float val = logf(g_sortp[i]) + g;
    uint32_t ob = __float_as_uint(val);
    ob = (ob & 0x80000000u) ? ~ob : (ob | 0x80000000u);  // order-preserving
    unsigned long long pk =
        (((unsigned long long)ob) << 32) |
        (unsigned long long)(0xFFFFFFFFu - (uint32_t)i);  // tie -> smaller i
    atomicMax(&g_best, pk);
}

// __output__ is float32: write the token id as a float VALUE.
__global__ void k_out(float* out) {
    unsigned long long bst = g_best;
    uint32_t i = 0xFFFFFFFFu - (uint32_t)(bst & 0xFFFFFFFFull);
    if (i >= V_DIM) i = 0;
    out[0] = (float)g_order[i];
}

// ---------------- launch ----------------
extern "C" void kernel_launch(void* const* d_in, const int* in_sizes, int n_in,
                              void* d_out, int out_size) {
    const float* batch = (const float*)d_in[0];
    const float* pw    = (const float*)d_in[1];
    const float* W     = (const float*)d_in[2];
    const float* bias  = (const float*)d_in[3];

    k_init<<<128, 256>>>();
    k_scoredot<<<S_LEN, 256>>>(batch, pw);
    k_softmax_scores<<<1, 1024>>>();
    k_pool_part<<<dim3(16, 64), 128>>>(batch);
    k_pool_reduce<<<8, 256>>>();
    k_logits_part<<<dim3(250, 4), 256>>>(W);
    k_logits_final<<<250, 256>>>(bias);
    k_maxl<<<1, 1024>>>();
    k_exp<<<250, 256>>>();
    k_zred<<<1, 256>>>();
    k_phist<<<250, 256>>>();
    k_scan<<<1, 1024>>>();
    k_scatter<<<250, 256>>>();
    k_rank<<<512, 256>>>();
    k_cummask<<<1, 1024>>>();
    k_argmax<<<250, 256>>>();
    k_out<<<1, 1>>>((float*)d_out);
}

// round 9
// speedup vs baseline: 131.1249x; 131.1249x over previous
#include <cuda_runtime.h>
#include <cstdint>
#include <cstddef>

#define S_LEN 4096
#define D_DIM 2048
#define V_DIM 64000
#define NBINS (1 << 20)     // bin = key >> 12
#define NGROUPS 1024        // 1024 bins per group
#define BIN_SMEM 2048

// ---------------- static scratch (no allocations allowed) ----------------
__device__ float  g_s[S_LEN];
__device__ float  g_scores[S_LEN];
__device__ double g_pool_part[64][D_DIM];
__device__ float  g_pooled[D_DIM];
__device__ double g_logit_part[4][V_DIM];
__device__ float  g_logits[V_DIM];
__device__ float  g_maxl;
__device__ float  g_e[V_DIM];
__device__ double g_zpart[256];
__device__ float  g_Z;
__device__ unsigned g_key[V_DIM];
__device__ unsigned g_hist[NBINS];
__device__ unsigned g_base[NBINS];     // within-group suffix-exclusive
__device__ unsigned g_fill[NBINS];
__device__ unsigned g_groupsum[NGROUPS];
__device__ unsigned g_groupbase[NGROUPS];  // cross-group suffix-exclusive
__device__ int      g_nbins;
__device__ int      g_binlist[NBINS];
__device__ unsigned g_slotkey[V_DIM];
__device__ int      g_slotidx[V_DIM];
__device__ float    g_sortp[V_DIM];
__device__ int      g_order[V_DIM];
__device__ unsigned char g_mask[V_DIM];
__device__ unsigned long long g_best;

// ---------------- threefry2x32 (bit-exact JAX PRNG) ----------------
__device__ __forceinline__ uint32_t rotl32(uint32_t v, int n) {
    return (v << n) | (v >> (32 - n));
}

__device__ __forceinline__ void threefry2x32(uint32_t k0, uint32_t k1,
                                             uint32_t& x0, uint32_t& x1) {
    uint32_t ks[3] = {k0, k1, k0 ^ k1 ^ 0x1BD11BDAu};
    const int rotA[4] = {13, 15, 26, 6};
    const int rotB[4] = {17, 29, 16, 24};
    x0 += ks[0]; x1 += ks[1];
#pragma unroll
    for (int i = 0; i < 5; i++) {
        const int* r = (i & 1) ? rotB : rotA;
#pragma unroll
        for (int k = 0; k < 4; k++) {
            x0 += x1;
            x1 = rotl32(x1, r[k]);
            x1 ^= x0;
        }
        x0 += ks[(i + 1) % 3];
        x1 += ks[(i + 2) % 3] + (uint32_t)(i + 1);
    }
}

// ---------------- kernels ----------------
__global__ void k_init() {
    int i = blockIdx.x * blockDim.x + threadIdx.x;  // 1M threads
    if (i < NBINS) { g_hist[i] = 0u; g_fill[i] = 0u; }
    if (i == 0) { g_best = 0ull; g_nbins = 0; }
}

// s[j] = batch[j,:] . pool_w  (exact fp32 products, order-free fp64 accumulate)
__global__ void k_scoredot(const float* __restrict__ batch,
                           const float* __restrict__ pw) {
    int j = blockIdx.x;
    const float* row = batch + (size_t)j * D_DIM;
    int t = threadIdx.x;  // 256
    double acc = 0.0;
#pragma unroll
    for (int k = 0; k < 8; k++) {
        int d = t + k * 256;
        acc += (double)(row[d] * pw[d]);
    }
    __shared__ double sm[256];
    sm[t] = acc;
    __syncthreads();
    for (int o = 128; o > 0; o >>= 1) {
        if (t < o) sm[t] += sm[t + o];
        __syncthreads();
    }
    if (t == 0) g_s[j] = (float)sm[0];
}

// softmax over S (single block)
__global__ void k_softmax_scores() {
    __shared__ float smx[1024];
    __shared__ double smd[1024];
    int t = threadIdx.x;
    float m = -3.4e38f;
    for (int i = t; i < S_LEN; i += 1024) m = fmaxf(m, g_s[i]);
    smx[t] = m;
    __syncthreads();
    for (int o = 512; o > 0; o >>= 1) {
        if (t < o) smx[t] = fmaxf(smx[t], smx[t + o]);
        __syncthreads();
    }
    float gm = smx[0];
    __syncthreads();
    double sum = 0.0;
    for (int i = t; i < S_LEN; i += 1024) {
        float e = expf(g_s[i] - gm);
        g_scores[i] = e;
        sum += (double)e;
    }
    smd[t] = sum;
    __syncthreads();
    for (int o = 512; o > 0; o >>= 1) {
        if (t < o) smd[t] += smd[t + o];
        __syncthreads();
    }
    float Z = (float)smd[0];
    __syncthreads();
    for (int i = t; i < S_LEN; i += 1024) g_scores[i] = g_scores[i] / Z;
}

// pooled partials: fp32 chunk-of-8 accumulation + fp64 chunk combine
// (chunk error ~1e-10 abs, far below 3.8e-7 logit rank gaps)
__global__ void k_pool_part(const float* __restrict__ batch) {
    int d = blockIdx.x * 128 + threadIdx.x;  // grid.x = 16
    int c = blockIdx.y;                       // 0..63
    int j0 = c * 64;
    double acc = 0.0;
#pragma unroll
    for (int jj = 0; jj < 64; jj += 8) {
        float ch = 0.f;
#pragma unroll
        for (int k = 0; k < 8; k++) {
            int j = j0 + jj + k;
            ch = fmaf(g_scores[j], batch[(size_t)j * D_DIM + d], ch);
        }
        acc += (double)ch;
    }
    g_pool_part[c][d] = acc;
}

__global__ void k_pool_reduce() {
    int d = blockIdx.x * 256 + threadIdx.x;  // grid 8
    double s = 0.0;
    for (int c = 0; c < 64; c++) s += g_pool_part[c][d];
    g_pooled[d] = (float)s;
}

// big GEMV: fp32 chunk-of-16 (4 interleaved FMA chains) + fp64 combine.
// 32 DADD/thread instead of 512; chunk rounding ~1e-10 << rank gaps.
__global__ void k_logits_part(const float* __restrict__ W) {
    int v = blockIdx.x * 256 + threadIdx.x;  // grid.x = 250
    int seg = blockIdx.y;                     // 0..3
    int d0 = seg * 512;
    __shared__ float sp[512];
    for (int i = threadIdx.x; i < 512; i += 256) sp[i] = g_pooled[d0 + i];
    __syncthreads();
    const float* wp = W + (size_t)d0 * V_DIM + v;
    double acc = 0.0;
#pragma unroll 2
    for (int d = 0; d < 512; d += 16) {
        float c0 = 0.f, c1 = 0.f, c2 = 0.f, c3 = 0.f;
#pragma unroll
        for (int k = 0; k < 16; k += 4) {
            size_t base = (size_t)(d + k) * V_DIM;
            c0 = fmaf(sp[d + k + 0], wp[base + 0 * (size_t)V_DIM], c0);
            c1 = fmaf(sp[d + k + 1], wp[base + 1 * (size_t)V_DIM], c1);
            c2 = fmaf(sp[d + k + 2], wp[base + 2 * (size_t)V_DIM], c2);
            c3 = fmaf(sp[d + k + 3], wp[base + 3 * (size_t)V_DIM], c3);
        }
        acc += (double)((c0 + c1) + (c2 + c3));
    }
    g_logit_part[seg][v] = acc;
}

__global__ void k_logits_final(const float* __restrict__ b) {
    int v = blockIdx.x * 256 + threadIdx.x;  // grid 250
    double s = g_logit_part[0][v] + g_logit_part[1][v] +
               g_logit_part[2][v] + g_logit_part[3][v];
    float m = (float)s;
    m = m + b[v];            // reference adds bias in fp32
    g_logits[v] = 0.7f * m;  // TEMPERATURE
}

__global__ void k_maxl() {
    __shared__ float sm[1024];
    int t = threadIdx.x;
    float m = -3.4e38f;
    for (int i = t; i < V_DIM; i += 1024) m = fmaxf(m, g_logits[i]);
    sm[t] = m;
    __syncthreads();
    for (int o = 512; o > 0; o >>= 1) {
        if (t < o) sm[t] = fmaxf(sm[t], sm[t + o]);
        __syncthreads();
    }
    if (t == 0) g_maxl = sm[0];
}

__global__ void k_exp() {
    int v = blockIdx.x * 256 + threadIdx.x;
    float e = expf(g_logits[v] - g_maxl);
    g_e[v] = e;
    __shared__ double sd[256];
    sd[threadIdx.x] = (double)e;
    __syncthreads();
    for (int o = 128; o > 0; o >>= 1) {
        if (threadIdx.x < o) sd[threadIdx.x] += sd[threadIdx.x + o];
        __syncthreads();
    }
    if (threadIdx.x == 0) g_zpart[blockIdx.x] = sd[0];
}

__global__ void k_zred() {
    __shared__ double sd[256];
    int t = threadIdx.x;
    sd[t] = (t < 250) ? g_zpart[t] : 0.0;
    __syncthreads();
    for (int o = 128; o > 0; o >>= 1) {
        if (t < o) sd[t] += sd[t + o];
        __syncthreads();
    }
    if (t == 0) g_Z = (float)sd[0];
}

__global__ void k_phist() {
    int v = blockIdx.x * 256 + threadIdx.x;
    float p = g_e[v] / g_Z;             // IEEE fp32 division
    unsigned key = __float_as_uint(p);  // p > 0 -> bits monotone
    g_key[v] = key;
    atomicAdd(&g_hist[key >> 12], 1u);
}

// scan A: per-group (1024 bins) suffix-exclusive scan + group sums + binlist
__global__ void k_scanA() {
    int g = blockIdx.x;       // 0..1023
    int t = threadIdx.x;      // 1024
    int b = g * 1024 + t;
    unsigned h = g_hist[b];
    __shared__ unsigned s[1024];
    s[t] = h;
    __syncthreads();
    for (int off = 1; off < 1024; off <<= 1) {
        unsigned add = (t >= off) ? s[t - off] : 0u;
        __syncthreads();
        s[t] += add;
        __syncthreads();
    }
    unsigned total = s[1023];
    g_base[b] = total - s[t];  // within-group count strictly above b
    if (t == 0) g_groupsum[g] = total;
    if (h > 0) {
        int p = atomicAdd(&g_nbins, 1);
        g_binlist[p] = b;
    }
}

// scan B: suffix-exclusive scan across 1024 group sums
__global__ void k_scanB() {
    int t = threadIdx.x;  // 1024
    __shared__ unsigned s[1024];
    s[t] = g_groupsum[t];
    __syncthreads();
    for (int off = 1; off < 1024; off <<= 1) {
        unsigned add = (t >= off) ? s[t - off] : 0u;
        __syncthreads();
        s[t] += add;
        __syncthreads();
    }
    unsigned total = s[1023];
    g_groupbase[t] = total - s[t];  // count in groups strictly above t
}

__global__ void k_scatter() {
    int v = blockIdx.x * 256 + threadIdx.x;
    unsigned key = g_key[v];
    unsigned b = key >> 12;
    unsigned pos = g_groupbase[b >> 10] + g_base[b] + atomicAdd(&g_fill[b], 1u);
    g_slotkey[pos] = key;
    g_slotidx[pos] = v;
}

// exact rank within bin: descending key, ties by ascending original index
__global__ void k_rank() {
    __shared__ unsigned sk[BIN_SMEM];
    __shared__ int si[BIN_SMEM];
    int nb = g_nbins;
    for (int bi = blockIdx.x; bi < nb; bi += gridDim.x) {
        int b = g_binlist[bi];
        unsigned c = g_hist[b];
        unsigned base = g_groupbase[b >> 10] + g_base[b];
        if (c <= BIN_SMEM) {
            for (unsigned e = threadIdx.x; e < c; e += blockDim.x) {
                sk[e] = g_slotkey[base + e];
                si[e] = g_slotidx[base + e];
            }
            __syncthreads();
            for (unsigned e = threadIdx.x; e < c; e += blockDim.x) {
                unsigned ke = sk[e];
                int ide = si[e];
                unsigned r = 0;
                for (unsigned u = 0; u < c; u++) {
                    unsigned ku = sk[u];
                    r += (ku > ke) || (ku == ke && si[u] < ide);
                }
                g_sortp[base + r] = __uint_as_float(ke);
                g_order[base + r] = ide;
            }
            __syncthreads();
        } else {  // fallback (should not trigger with 2^20 bins)
            for (unsigned e = threadIdx.x; e < c; e += blockDim.x) {
                unsigned ke = g_slotkey[base + e];
                int ide = g_slotidx[base + e];
                unsigned r = 0;
                for (unsigned u = 0; u < c; u++) {
                    unsigned ku = g_slotkey[base + u];
                    r += (ku > ke) || (ku == ke && g_slotidx[base + u] < ide);
                }
                g_sortp[base + r] = __uint_as_float(ke);
                g_order[base + r] = ide;
            }
            __syncthreads();
        }
    }
}

// inclusive cumsum (fp64) + top-p mask
__global__ void k_cummask() {
    __shared__ double sd[1024];
    int t = threadIdx.x;
    int i0 = t * 64;
    double s = 0.0;
    for (int k = 0; k < 64; k++) {
        int i = i0 + k;
        if (i < V_DIM) s += (double)g_sortp[i];
    }
    sd[t] = s;
    __syncthreads();
    for (int off = 1; off < 1024; off <<= 1) {
        double add = (t >= off) ? sd[t - off] : 0.0;
        __syncthreads();
        sd[t] += add;
        __syncthreads();
    }
    double run = (t > 0) ? sd[t - 1] : 0.0;
    for (int k = 0; k < 64; k++) {
        int i = i0 + k;
        if (i < V_DIM) {
            run += (double)g_sortp[i];
            g_mask[i] = (run <= 0.5) ? 1 : 0;
        }
    }
}

// gumbel-argmax; JAX partitionable threefry, 32-bit draw = y0 ^ y1
__global__ void k_argmax() {
    int i = blockIdx.x * 256 + threadIdx.x;
    if (i >= V_DIM) return;
    if (!g_mask[i]) return;
    uint32_t x0 = 0u, x1 = (uint32_t)i;
    threefry2x32(0u, 42u, x0, x1);
    uint32_t bits = x0 ^ x1;
    float f = __uint_as_float((bits >> 9) | 0x3f800000u) - 1.0f;  // [0,1)
    float u = (f > 0.0f) ? f : 1.17549435e-38f;
    float g = -logf(-logf(u));
    float val = logf(g_sortp[i]) + g;
    uint32_t ob = __float_as_uint(val);
    ob = (ob & 0x80000000u) ? ~ob : (ob | 0x80000000u);
    unsigned long long pk =
        (((unsigned long long)ob) << 32) |
        (unsigned long long)(0xFFFFFFFFu - (uint32_t)i);
    atomicMax(&g_best, pk);
}

__global__ void k_out(float* out) {
    unsigned long long bst = g_best;
    uint32_t i = 0xFFFFFFFFu - (uint32_t)(bst & 0xFFFFFFFFull);
    if (i >= V_DIM) i = 0;
    out[0] = (float)g_order[i];
}

// ---------------- launch ----------------
extern "C" void kernel_launch(void* const* d_in, const int* in_sizes, int n_in,
                              void* d_out, int out_size) {
    const float* batch = (const float*)d_in[0];
    const float* pw    = (const float*)d_in[1];
    const float* W     = (const float*)d_in[2];
    const float* bias  = (const float*)d_in[3];

    k_init<<<NBINS / 256, 256>>>();
    k_scoredot<<<S_LEN, 256>>>(batch, pw);
    k_softmax_scores<<<1, 1024>>>();
    k_pool_part<<<dim3(16, 64), 128>>>(batch);
    k_pool_reduce<<<8, 256>>>();
    k_logits_part<<<dim3(250, 4), 256>>>(W);
    k_logits_final<<<250, 256>>>(bias);
    k_maxl<<<1, 1024>>>();
    k_exp<<<250, 256>>>();
    k_zred<<<1, 256>>>();
    k_phist<<<250, 256>>>();
    k_scanA<<<NGROUPS, 1024>>>();
    k_scanB<<<1, 1024>>>();
    k_scatter<<<250, 256>>>();
    k_rank<<<1024, 256>>>();
    k_cummask<<<1, 1024>>>();
    k_argmax<<<250, 256>>>();
    k_out<<<1, 1>>>((float*)d_out);
}